// round 14
// baseline (speedup 1.0000x reference)
#include <cuda_runtime.h>
#include <cuda_fp16.h>
#include <math.h>

#define NIMG 12
#define N 256
#define NA 180
#define P 258   // padded dim (zero border, index = coord+1)

// Scratch (device globals; no allocation allowed)
__device__ float4  g_quad [NIMG * P * P]; // [img][y+1][x+1] = (p00,p01,p10,p11) at (y,x)
__device__ float4  g_quadT[NIMG * P * P]; // [img][x+1][y+1] = (p00,p10,p01,p11) at (y,x)
__device__ float   g_sino[NIMG * N * NA]; // [img][n][a]
__device__ float   g_Q[NIMG * N * NA];
__device__ float   g_K[NIMG * N * NA];
__device__ float   g_V[NIMG * N * NA];
__device__ float   g_att[NIMG * N * NA];  // [img][n][a]
__device__ __half2 g_filth[NIMG * NA * N];// [img][a][n] = h2(f[n], f[n+1])

__device__ __forceinline__ float pix(const float* im, int y, int x) {
    return ((unsigned)y < 256u && (unsigned)x < 256u) ? __ldg(im + (y << 8) + x) : 0.0f;
}

// ---------------------------------------------------------------------------
// K0: build padded fp32 quad images (normal + transposed layouts).
// ---------------------------------------------------------------------------
__global__ void k_prep(const float* __restrict__ x) {
    int r = blockIdx.x, img = blockIdx.y;
    const float* im = x + img * N * N;
    float4* d  = g_quad  + (size_t)img * P * P + (size_t)r * P;
    float4* dt = g_quadT + (size_t)img * P * P + (size_t)r * P;
    for (int c = threadIdx.x; c < P; c += blockDim.x) {
        int y = r - 1, xx = c - 1;
        d[c]  = make_float4(pix(im, y, xx),     pix(im, y, xx + 1),
                            pix(im, y + 1, xx), pix(im, y + 1, xx + 1));
        int ty = c - 1, tx = r - 1;
        dt[c] = make_float4(pix(im, ty, tx),     pix(im, ty + 1, tx),
                            pix(im, ty, tx + 1), pix(im, ty + 1, tx + 1));
    }
}

// ---------------------------------------------------------------------------
// K1: Radon transform. block=(angle, img). Warp lanes tile (A_n x A_y) of
// (detector n, sum index y), shape chosen per angle to minimize distinct
// image rows per warp access (L1tex wavefronts). Partial y-sums reduced
// across lanes with shfl_xor.
// ---------------------------------------------------------------------------
__global__ void k_radon() {
    const int a = blockIdx.x, img = blockIdx.y;
    const int t = threadIdx.x, warp = t >> 5, lane = t & 31;
    float th = (float)((double)a * M_PI / 180.0);
    float c = cosf(th), s = sinf(th);
    float am = fminf(fabsf(c), fabsf(s)), aM = fmaxf(fabsf(c), fabsf(s));

    // pick A_n in {8,16,32} minimizing row span A_n*am + (32/A_n)*aM
    float s8 = 8.f * am + 4.f * aM, s16 = 16.f * am + 2.f * aM, s32 = 32.f * am + aM;
    int shift = (s8 <= s16 && s8 <= s32) ? 3 : ((s16 <= s32) ? 4 : 5);
    const int An = 1 << shift, Ay = 32 >> shift;
    const int ny = lane & (An - 1), yy = lane >> shift;

    const bool norm = fabsf(c) >= fabsf(s);
    const float4* im4 = (norm ? g_quad : g_quadT) + (size_t)img * P * P;
    const float4 Z = make_float4(0.f, 0.f, 0.f, 0.f);

    for (int nb = warp; nb < (256 >> shift); nb += 8) {
        int n = (nb << shift) + ny;
        float bx = c * (float)n - 128.0f * (c + s - 1.0f);
        float by = -s * (float)n - 128.0f * (c - s - 1.0f);
        float acc = 0.0f;

        if (norm) {
            #pragma unroll 4
            for (int y = yy; y < 256; y += Ay) {
                float sx = bx + s * (float)y;
                float sy = by + c * (float)y;
                float fx0 = floorf(sx), fy0 = floorf(sy);
                int ix = (int)fx0, iy = (int)fy0;
                float fx = sx - fx0, fy = sy - fy0;
                int rr = iy + 1, cc = ix + 1;
                bool ok = ((unsigned)rr < (unsigned)P) & ((unsigned)cc < (unsigned)P);
                float4 q = ok ? __ldg(im4 + rr * P + cc) : Z;
                acc += (1.0f - fy) * ((1.0f - fx) * q.x + fx * q.y)
                     + fy * ((1.0f - fx) * q.z + fx * q.w);
            }
        } else {
            #pragma unroll 4
            for (int y = yy; y < 256; y += Ay) {
                float sx = bx + s * (float)y;
                float sy = by + c * (float)y;
                float fx0 = floorf(sx), fy0 = floorf(sy);
                int ix = (int)fx0, iy = (int)fy0;
                float fx = sx - fx0, fy = sy - fy0;
                int rr = ix + 1, cc = iy + 1;   // transposed: [x+1][y+1]
                bool ok = ((unsigned)rr < (unsigned)P) & ((unsigned)cc < (unsigned)P);
                float4 q = ok ? __ldg(im4 + rr * P + cc) : Z;
                // q = (p00, p10, p01, p11)
                acc += (1.0f - fy) * ((1.0f - fx) * q.x + fx * q.z)
                     + fy * ((1.0f - fx) * q.y + fx * q.w);
            }
        }

        // reduce partial sums across the y-sublanes (lanes spaced An apart)
        for (int off = An; off < 32; off <<= 1)
            acc += __shfl_xor_sync(0xffffffffu, acc, off);
        if (yy == 0)
            g_sino[(img * N + n) * NA + a] = acc;
    }
}

// ---------------------------------------------------------------------------
// K2: QKV projections. block=(32-row tile, img, matrix), 256 thr.
// ---------------------------------------------------------------------------
__global__ void k_qkv(const float* __restrict__ Wq, const float* __restrict__ bq,
                      const float* __restrict__ Wk, const float* __restrict__ bk,
                      const float* __restrict__ Wv, const float* __restrict__ bv) {
    int img = blockIdx.y, r0 = blockIdx.x * 32, m = blockIdx.z;
    __shared__ float As[32 * NA];
    const float* src = g_sino + (img * N + r0) * NA;
    for (int i = threadIdx.x; i < 32 * NA; i += 256) As[i] = src[i];
    __syncthreads();

    int r = threadIdx.x >> 3, sub = threadIdx.x & 7;
    const float4* arow = (const float4*)(As + r * NA);

    const float* W = (m == 0) ? Wq : (m == 1) ? Wk : Wv;
    const float* b = (m == 0) ? bq : (m == 1) ? bk : bv;
    float* outbase = (m == 0) ? g_Q : (m == 1) ? g_K : g_V;
    float* out = outbase + (img * N + r0 + r) * NA;

    for (int j = sub; j < NA; j += 8) {
        const float4* wrow = (const float4*)(W + j * NA);
        float acc = 0.0f;
        #pragma unroll
        for (int k = 0; k < 45; k++) {
            float4 av = arow[k];
            float4 wv = __ldg(wrow + k);
            acc += av.x * wv.x + av.y * wv.y + av.z * wv.z + av.w * wv.w;
        }
        out[j] = acc + __ldg(b + j);
    }
}

// ---------------------------------------------------------------------------
// K3: softmax attention. block=(8-qrow tile, img), 256 threads.
// warp w = q-row w; lane = score column within a 32-wide K tile.
// ---------------------------------------------------------------------------
__global__ void k_attn() {
    const int img = blockIdx.y, q0 = blockIdx.x * 8;
    __shared__ float Qs[8 * NA];
    __shared__ float Ts[32 * NA];      // streamed K/V tile (23KB)
    __shared__ float S[8][257];        // padded scores

    const int t = threadIdx.x;
    const int row = t >> 5, lane = t & 31;

    const float* Qg = g_Q + (img * N + q0) * NA;
    for (int i = t; i < 8 * NA; i += 256) Qs[i] = Qg[i];

    const float* Kg = g_K + img * N * NA;
    const float scale = 0.07453559924999299f;  // 1/sqrt(180)

    const float4* qrow = (const float4*)(Qs + row * NA);
    float loc[8];

    #pragma unroll 1
    for (int kt = 0; kt < 8; kt++) {
        __syncthreads();
        const float* src = Kg + kt * 32 * NA;
        for (int i = t; i < 32 * NA; i += 256) Ts[i] = src[i];
        __syncthreads();
        const float4* krow = (const float4*)(Ts + lane * NA);
        float acc = 0.0f;
        #pragma unroll
        for (int j = 0; j < 45; j++) {
            float4 qv = qrow[j];
            float4 kv = krow[j];
            acc += qv.x * kv.x + qv.y * kv.y + qv.z * kv.z + qv.w * kv.w;
        }
        loc[kt] = acc * scale;   // score for column kt*32+lane
    }

    float mx = loc[0];
    #pragma unroll
    for (int m = 1; m < 8; m++) mx = fmaxf(mx, loc[m]);
    #pragma unroll
    for (int o = 16; o > 0; o >>= 1) mx = fmaxf(mx, __shfl_xor_sync(0xffffffffu, mx, o));
    float sum = 0.0f;
    #pragma unroll
    for (int m = 0; m < 8; m++) { loc[m] = expf(loc[m] - mx); sum += loc[m]; }
    #pragma unroll
    for (int o = 16; o > 0; o >>= 1) sum += __shfl_xor_sync(0xffffffffu, sum, o);
    float inv = 1.0f / sum;
    #pragma unroll
    for (int m = 0; m < 8; m++) S[row][m * 32 + lane] = loc[m] * inv;

    const float* Vg = g_V + img * N * NA;
    float acc[6];
    #pragma unroll
    for (int m = 0; m < 6; m++) acc[m] = 0.0f;

    #pragma unroll 1
    for (int vt = 0; vt < 8; vt++) {
        __syncthreads();
        const float* src = Vg + vt * 32 * NA;
        for (int i = t; i < 32 * NA; i += 256) Ts[i] = src[i];
        __syncthreads();
        #pragma unroll
        for (int k = 0; k < 32; k++) {
            float sc = S[row][vt * 32 + k];
            const float* vr = Ts + k * NA + lane;
            #pragma unroll
            for (int m = 0; m < 6; m++) {
                int j = lane + 32 * m;
                if (j < NA) acc[m] += sc * vr[32 * m];
            }
        }
    }

    float* out = g_att + (img * N + q0 + row) * NA;
    #pragma unroll
    for (int m = 0; m < 6; m++) {
        int j = lane + 32 * m;
        if (j < NA) out[j] = acc[m];
    }
}

// ---------------------------------------------------------------------------
// K4: ramp filter = sparse conv (exactly equal to FFT ramp filtering).
// Emits __half2 pairs (f[n], f[n+1]) for single-LDG.32 backprojection.
// (fp16 here is downstream of softmax and linear to the output: safe.)
// ---------------------------------------------------------------------------
__global__ void k_filter() {
    int a = blockIdx.x, img = blockIdx.y, n = threadIdx.x;
    __shared__ float col[768];   // [0..255]=0, [256..511]=data, [512..767]=0
    __shared__ float res[256];
    __shared__ float wt[128];
    col[n] = 0.0f;
    col[n + 512] = 0.0f;
    if (n < 128) {
        float d = 2.0f * n + 1.0f;
        wt[n] = -0.20264236728467555f / (d * d);  // -2/pi^2 / d^2
    }
    col[256 + n] = g_att[(img * N + n) * NA + a];
    __syncthreads();
    float acc = 0.5f * col[256 + n];
    #pragma unroll 8
    for (int i = 0; i < 128; i++) {
        int d = 2 * i + 1;
        acc += wt[i] * (col[256 + n - d] + col[256 + n + d]);
    }
    res[n] = acc;
    __syncthreads();
    float hi = (n < 255) ? res[n + 1] : 0.0f;  // frac==0 when i0==255 -> .y unused
    g_filth[(img * NA + a) * N + n] = __floats2half2_rn(res[n], hi);
}

// ---------------------------------------------------------------------------
// K5: filtered backprojection. block=(row i, img), thread = col j.
// Single __half2 load (4B) per angle gives both interpolation endpoints.
// ---------------------------------------------------------------------------
__global__ void k_back(float* __restrict__ out) {
    int i = blockIdx.x, img = blockIdx.y, j = threadIdx.x;
    __shared__ float cs[NA], sn[NA];
    if (threadIdx.x < NA) {
        float th = (float)((double)threadIdx.x * M_PI / 180.0);
        cs[threadIdx.x] = cosf(th);
        sn[threadIdx.x] = sinf(th);
    }
    __syncthreads();

    float xp = (float)(i - 128);
    float yp = (float)(j - 128);
    const __half2* F = g_filth + (size_t)img * NA * N;
    float acc = 0.0f;
    #pragma unroll 4
    for (int a = 0; a < NA; a++) {
        float t = yp * cs[a] - xp * sn[a] + 128.0f;
        if (t >= 0.0f && t <= 255.0f) {
            float fl = floorf(t);
            int i0 = (int)fl;
            float fr = t - fl;
            float2 v = __half22float2(__ldg(F + a * N + i0));
            acc += (1.0f - fr) * v.x + fr * v.y;
        }
    }
    int r2 = (i - 128) * (i - 128) + (j - 128) * (j - 128);
    out[(img * N + i) * N + j] = (r2 <= 16384) ? acc * 0.008726646259971648f : 0.0f;
}

// ---------------------------------------------------------------------------
extern "C" void kernel_launch(void* const* d_in, const int* in_sizes, int n_in,
                              void* d_out, int out_size) {
    const float* x  = (const float*)d_in[0];
    const float* Wq = (const float*)d_in[1];
    const float* bq = (const float*)d_in[2];
    const float* Wk = (const float*)d_in[3];
    const float* bk = (const float*)d_in[4];
    const float* Wv = (const float*)d_in[5];
    const float* bv = (const float*)d_in[6];
    float* out = (float*)d_out;

    k_prep  <<<dim3(P, NIMG), 256>>>(x);
    k_radon <<<dim3(NA, NIMG), 256>>>();
    k_qkv   <<<dim3(8, NIMG, 3), 256>>>(Wq, bq, Wk, bk, Wv, bv);
    k_attn  <<<dim3(32, NIMG), 256>>>();
    k_filter<<<dim3(NA, NIMG), 256>>>();
    k_back  <<<dim3(256, NIMG), 256>>>(out);
}

// round 15
// speedup vs baseline: 1.0273x; 1.0273x over previous
#include <cuda_runtime.h>
#include <cuda_fp16.h>
#include <math.h>

#define NIMG 12
#define N 256
#define NA 180
#define P 258   // padded dim (zero border, index = coord+1)

// Scratch (device globals; no allocation allowed)
__device__ float4  g_quad [NIMG * P * P]; // [img][y+1][x+1] = (p00,p01,p10,p11) at (y,x)
__device__ float4  g_quadT[NIMG * P * P]; // [img][x+1][y+1] = (p00,p10,p01,p11) at (y,x)
__device__ float   g_sino[NIMG * N * NA]; // [img][n][a]
__device__ float   g_Q[NIMG * N * NA];
__device__ float   g_K[NIMG * N * NA];
__device__ float   g_V[NIMG * N * NA];
__device__ float   g_att[NIMG * N * NA];  // [img][n][a]
__device__ __half2 g_filth[NIMG * NA * N];// [img][a][n] = h2(f[n], f[n+1])

__device__ __forceinline__ float pix(const float* im, int y, int x) {
    return ((unsigned)y < 256u && (unsigned)x < 256u) ? __ldg(im + (y << 8) + x) : 0.0f;
}

// ---------------------------------------------------------------------------
// K0: build padded fp32 quad images (normal + transposed layouts).
// ---------------------------------------------------------------------------
__global__ void k_prep(const float* __restrict__ x) {
    int r = blockIdx.x, img = blockIdx.y;
    const float* im = x + img * N * N;
    float4* d  = g_quad  + (size_t)img * P * P + (size_t)r * P;
    float4* dt = g_quadT + (size_t)img * P * P + (size_t)r * P;
    for (int c = threadIdx.x; c < P; c += blockDim.x) {
        int y = r - 1, xx = c - 1;
        d[c]  = make_float4(pix(im, y, xx),     pix(im, y, xx + 1),
                            pix(im, y + 1, xx), pix(im, y + 1, xx + 1));
        int ty = c - 1, tx = r - 1;
        dt[c] = make_float4(pix(im, ty, tx),     pix(im, ty + 1, tx),
                            pix(im, ty, tx + 1), pix(im, ty + 1, tx + 1));
    }
}

// ---------------------------------------------------------------------------
// K1: Radon transform (R12 proven form). block=(angle, img), thread n.
// One predicated LDG.128 per bilinear sample; layout chosen per angle.
// ---------------------------------------------------------------------------
__global__ void k_radon() {
    int a = blockIdx.x, img = blockIdx.y, n = threadIdx.x;
    float th = (float)((double)a * M_PI / 180.0);
    float c = cosf(th), s = sinf(th);
    float bx = c * (float)n - 128.0f * (c + s - 1.0f);
    float by = -s * (float)n - 128.0f * (c - s - 1.0f);
    float acc = 0.0f;
    const float4 Z = make_float4(0.f, 0.f, 0.f, 0.f);

    if (fabsf(c) >= fabsf(s)) {
        const float4* im4 = g_quad + (size_t)img * P * P;
        #pragma unroll 4
        for (int y = 0; y < N; y++) {
            float sx = bx + s * (float)y;
            float sy = by + c * (float)y;
            float fx0 = floorf(sx), fy0 = floorf(sy);
            int ix = (int)fx0, iy = (int)fy0;
            float fx = sx - fx0, fy = sy - fy0;
            int rr = iy + 1, cc = ix + 1;
            bool ok = ((unsigned)rr < (unsigned)P) & ((unsigned)cc < (unsigned)P);
            float4 q = ok ? __ldg(im4 + rr * P + cc) : Z;
            acc += (1.0f - fy) * ((1.0f - fx) * q.x + fx * q.y)
                 + fy * ((1.0f - fx) * q.z + fx * q.w);
        }
    } else {
        const float4* imT = g_quadT + (size_t)img * P * P;
        #pragma unroll 4
        for (int y = 0; y < N; y++) {
            float sx = bx + s * (float)y;
            float sy = by + c * (float)y;
            float fx0 = floorf(sx), fy0 = floorf(sy);
            int ix = (int)fx0, iy = (int)fy0;
            float fx = sx - fx0, fy = sy - fy0;
            int rr = ix + 1, cc = iy + 1;   // transposed indexing: [x+1][y+1]
            bool ok = ((unsigned)rr < (unsigned)P) & ((unsigned)cc < (unsigned)P);
            float4 q = ok ? __ldg(imT + rr * P + cc) : Z;
            // q = (p00, p10, p01, p11)
            acc += (1.0f - fy) * ((1.0f - fx) * q.x + fx * q.z)
                 + fy * ((1.0f - fx) * q.y + fx * q.w);
        }
    }
    g_sino[(img * N + n) * NA + a] = acc;
}

// ---------------------------------------------------------------------------
// K2: QKV projections. block=(32-row tile, img, matrix), 256 thr.
// ---------------------------------------------------------------------------
__global__ void k_qkv(const float* __restrict__ Wq, const float* __restrict__ bq,
                      const float* __restrict__ Wk, const float* __restrict__ bk,
                      const float* __restrict__ Wv, const float* __restrict__ bv) {
    int img = blockIdx.y, r0 = blockIdx.x * 32, m = blockIdx.z;
    __shared__ float As[32 * NA];
    const float* src = g_sino + (img * N + r0) * NA;
    for (int i = threadIdx.x; i < 32 * NA; i += 256) As[i] = src[i];
    __syncthreads();

    int r = threadIdx.x >> 3, sub = threadIdx.x & 7;
    const float4* arow = (const float4*)(As + r * NA);

    const float* W = (m == 0) ? Wq : (m == 1) ? Wk : Wv;
    const float* b = (m == 0) ? bq : (m == 1) ? bk : bv;
    float* outbase = (m == 0) ? g_Q : (m == 1) ? g_K : g_V;
    float* out = outbase + (img * N + r0 + r) * NA;

    for (int j = sub; j < NA; j += 8) {
        const float4* wrow = (const float4*)(W + j * NA);
        float acc = 0.0f;
        #pragma unroll
        for (int k = 0; k < 45; k++) {
            float4 av = arow[k];
            float4 wv = __ldg(wrow + k);
            acc += av.x * wv.x + av.y * wv.y + av.z * wv.z + av.w * wv.w;
        }
        out[j] = acc + __ldg(b + j);
    }
}

// ---------------------------------------------------------------------------
// K3: softmax attention. block=(8-qrow tile, img), 256 threads.
// QK^T: warp w = q-row w, lane = score column within a 32-wide K tile.
// S@V:  warp output as float4 chunks (cols 4*lane and 4*(lane+32)).
// ---------------------------------------------------------------------------
__global__ void k_attn() {
    const int img = blockIdx.y, q0 = blockIdx.x * 8;
    __shared__ float Qs[8 * NA];
    __shared__ float Ts[32 * NA];      // streamed K/V tile (23KB)
    __shared__ float S[8][257];        // padded scores

    const int t = threadIdx.x;
    const int row = t >> 5, lane = t & 31;

    const float* Qg = g_Q + (img * N + q0) * NA;
    for (int i = t; i < 8 * NA; i += 256) Qs[i] = Qg[i];

    const float* Kg = g_K + img * N * NA;
    const float scale = 0.07453559924999299f;  // 1/sqrt(180)

    const float4* qrow = (const float4*)(Qs + row * NA);
    float loc[8];

    #pragma unroll 1
    for (int kt = 0; kt < 8; kt++) {
        __syncthreads();
        const float* src = Kg + kt * 32 * NA;
        for (int i = t; i < 32 * NA; i += 256) Ts[i] = src[i];
        __syncthreads();
        const float4* krow = (const float4*)(Ts + lane * NA);
        float acc = 0.0f;
        #pragma unroll
        for (int j = 0; j < 45; j++) {
            float4 qv = qrow[j];
            float4 kv = krow[j];
            acc += qv.x * kv.x + qv.y * kv.y + qv.z * kv.z + qv.w * kv.w;
        }
        loc[kt] = acc * scale;   // score for column kt*32+lane
    }

    float mx = loc[0];
    #pragma unroll
    for (int m = 1; m < 8; m++) mx = fmaxf(mx, loc[m]);
    #pragma unroll
    for (int o = 16; o > 0; o >>= 1) mx = fmaxf(mx, __shfl_xor_sync(0xffffffffu, mx, o));
    float sum = 0.0f;
    #pragma unroll
    for (int m = 0; m < 8; m++) { loc[m] = expf(loc[m] - mx); sum += loc[m]; }
    #pragma unroll
    for (int o = 16; o > 0; o >>= 1) sum += __shfl_xor_sync(0xffffffffu, sum, o);
    float inv = 1.0f / sum;
    #pragma unroll
    for (int m = 0; m < 8; m++) S[row][m * 32 + lane] = loc[m] * inv;

    // att = S @ V. Warp computes its q-row's 180 outputs as 45 float4 chunks:
    // chunk m0 = lane (all lanes), chunk m1 = lane+32 (lanes 0..12).
    const float* Vg = g_V + img * N * NA;
    const bool has2 = (lane < 13);
    float4 acc0 = make_float4(0.f, 0.f, 0.f, 0.f);
    float4 acc1 = make_float4(0.f, 0.f, 0.f, 0.f);

    #pragma unroll 1
    for (int vt = 0; vt < 8; vt++) {
        __syncthreads();
        const float* src = Vg + vt * 32 * NA;
        for (int i = t; i < 32 * NA; i += 256) Ts[i] = src[i];
        __syncthreads();
        #pragma unroll
        for (int k = 0; k < 32; k++) {
            float sc = S[row][vt * 32 + k];
            const float4* vr4 = (const float4*)(Ts + k * NA);
            float4 v0 = vr4[lane];
            acc0.x += sc * v0.x; acc0.y += sc * v0.y;
            acc0.z += sc * v0.z; acc0.w += sc * v0.w;
            if (has2) {
                float4 v1 = vr4[lane + 32];
                acc1.x += sc * v1.x; acc1.y += sc * v1.y;
                acc1.z += sc * v1.z; acc1.w += sc * v1.w;
            }
        }
    }

    float4* out4 = (float4*)(g_att + (img * N + q0 + row) * NA);  // 720B-aligned rows
    out4[lane] = acc0;
    if (has2) out4[lane + 32] = acc1;
}

// ---------------------------------------------------------------------------
// K4: ramp filter = sparse conv (exactly equal to FFT ramp filtering).
// Emits __half2 pairs (f[n], f[n+1]) for single-LDG.32 backprojection.
// (fp16 here is downstream of softmax and linear to the output: safe.)
// ---------------------------------------------------------------------------
__global__ void k_filter() {
    int a = blockIdx.x, img = blockIdx.y, n = threadIdx.x;
    __shared__ float col[768];   // [0..255]=0, [256..511]=data, [512..767]=0
    __shared__ float res[256];
    __shared__ float wt[128];
    col[n] = 0.0f;
    col[n + 512] = 0.0f;
    if (n < 128) {
        float d = 2.0f * n + 1.0f;
        wt[n] = -0.20264236728467555f / (d * d);  // -2/pi^2 / d^2
    }
    col[256 + n] = g_att[(img * N + n) * NA + a];
    __syncthreads();
    float acc = 0.5f * col[256 + n];
    #pragma unroll 8
    for (int i = 0; i < 128; i++) {
        int d = 2 * i + 1;
        acc += wt[i] * (col[256 + n - d] + col[256 + n + d]);
    }
    res[n] = acc;
    __syncthreads();
    float hi = (n < 255) ? res[n + 1] : 0.0f;  // frac==0 when i0==255 -> .y unused
    g_filth[(img * NA + a) * N + n] = __floats2half2_rn(res[n], hi);
}

// ---------------------------------------------------------------------------
// K5: filtered backprojection. block=(row i, img), thread = col j.
// Single __half2 load (4B) per angle gives both interpolation endpoints.
// ---------------------------------------------------------------------------
__global__ void k_back(float* __restrict__ out) {
    int i = blockIdx.x, img = blockIdx.y, j = threadIdx.x;
    __shared__ float cs[NA], sn[NA];
    if (threadIdx.x < NA) {
        float th = (float)((double)threadIdx.x * M_PI / 180.0);
        cs[threadIdx.x] = cosf(th);
        sn[threadIdx.x] = sinf(th);
    }
    __syncthreads();

    float xp = (float)(i - 128);
    float yp = (float)(j - 128);
    const __half2* F = g_filth + (size_t)img * NA * N;
    float acc = 0.0f;
    #pragma unroll 4
    for (int a = 0; a < NA; a++) {
        float t = yp * cs[a] - xp * sn[a] + 128.0f;
        if (t >= 0.0f && t <= 255.0f) {
            float fl = floorf(t);
            int i0 = (int)fl;
            float fr = t - fl;
            float2 v = __half22float2(__ldg(F + a * N + i0));
            acc += (1.0f - fr) * v.x + fr * v.y;
        }
    }
    int r2 = (i - 128) * (i - 128) + (j - 128) * (j - 128);
    out[(img * N + i) * N + j] = (r2 <= 16384) ? acc * 0.008726646259971648f : 0.0f;
}

// ---------------------------------------------------------------------------
extern "C" void kernel_launch(void* const* d_in, const int* in_sizes, int n_in,
                              void* d_out, int out_size) {
    const float* x  = (const float*)d_in[0];
    const float* Wq = (const float*)d_in[1];
    const float* bq = (const float*)d_in[2];
    const float* Wk = (const float*)d_in[3];
    const float* bk = (const float*)d_in[4];
    const float* Wv = (const float*)d_in[5];
    const float* bv = (const float*)d_in[6];
    float* out = (float*)d_out;

    k_prep  <<<dim3(P, NIMG), 256>>>(x);
    k_radon <<<dim3(NA, NIMG), 256>>>();
    k_qkv   <<<dim3(8, NIMG, 3), 256>>>(Wq, bq, Wk, bk, Wv, bv);
    k_attn  <<<dim3(32, NIMG), 256>>>();
    k_filter<<<dim3(NA, NIMG), 256>>>();
    k_back  <<<dim3(256, NIMG), 256>>>(out);
}